// round 5
// baseline (speedup 1.0000x reference)
#include <cuda_runtime.h>
#include <math.h>

// Problem constants (fixed by the dataset)
#define NN 169343            // nodes
#define NE 1166243           // edges
#define ET (NE + NN)         // edges + self loops = 1335586
#define FDIM 128
#define NCLS 40

// ---------------- device scratch (no cudaMalloc allowed) ----------------
__device__ int   g_is64;                 // 1 if edge_index is int64, 0 if int32
__device__ int   g_deg[NN];              // in-degree (incl. self loop)
__device__ int   g_fill[NN];             // fill cursors for CSR build
__device__ int   g_rowptr[NN + 1];       // CSR row pointers (by dst)
__device__ int   g_bsum[256];            // scan block sums
__device__ int   g_adj[ET];              // CSR adjacency: src indices
__device__ float g_dinv[NN];             // deg^-1/2
__device__ float g_t[(size_t)NN * FDIM]; // GEMM output (dinv[src]-scaled)
__device__ float g_h[(size_t)NN * FDIM]; // aggregated hidden
__device__ float g_l[(size_t)NN * NCLS]; // layer-3 GEMM output

// ---------------- dtype detection for edge_index ----------------
// int64 little-endian: high 32-bit word of each value is 0 (values < 2^31).
// int32: odd int32 words are real node ids; P(all 1024 == 0) ~ 0.
__global__ void detect64_kernel(const int* __restrict__ w) {
    __shared__ int bad;
    if (threadIdx.x == 0) bad = 0;
    __syncthreads();
    for (int i = threadIdx.x; i < 1024; i += blockDim.x)
        if (w[2 * i + 1] != 0) atomicAdd(&bad, 1);
    __syncthreads();
    if (threadIdx.x == 0) g_is64 = (bad == 0) ? 1 : 0;
}

__device__ __forceinline__ int edge_src(const int* w, int e) {
    return g_is64 ? w[2 * e] : w[e];
}
__device__ __forceinline__ int edge_dst(const int* w, int e) {
    return g_is64 ? w[2 * (NE + e)] : w[NE + e];
}

// ---------------- preprocessing ----------------
__global__ void init_deg_kernel() {
    int i = blockIdx.x * blockDim.x + threadIdx.x;
    if (i < NN) { g_deg[i] = 1; g_fill[i] = 0; }  // 1 = self loop
}

__global__ void count_deg_kernel(const int* __restrict__ w) {
    int e = blockIdx.x * blockDim.x + threadIdx.x;
    if (e >= NE) return;
    atomicAdd(&g_deg[edge_dst(w, e)], 1);
}

__global__ void calc_dinv_kernel() {
    int i = blockIdx.x * blockDim.x + threadIdx.x;
    if (i < NN) g_dinv[i] = rsqrtf((float)g_deg[i]);
}

// Exclusive scan of g_deg into g_rowptr (3-kernel scheme)
#define SCAN_BLK 1024
__global__ void scan1_kernel() {
    __shared__ int sh[SCAN_BLK];
    int i = blockIdx.x * SCAN_BLK + threadIdx.x;
    int v = (i < NN) ? g_deg[i] : 0;
    sh[threadIdx.x] = v;
    __syncthreads();
    for (int off = 1; off < SCAN_BLK; off <<= 1) {
        int add = (threadIdx.x >= off) ? sh[threadIdx.x - off] : 0;
        __syncthreads();
        sh[threadIdx.x] += add;
        __syncthreads();
    }
    if (i < NN) g_rowptr[i + 1] = sh[threadIdx.x];
    if (threadIdx.x == SCAN_BLK - 1) g_bsum[blockIdx.x] = sh[threadIdx.x];
}

__global__ void scan2_kernel(int nb) {
    __shared__ int sh[256];
    int t = threadIdx.x;
    sh[t] = (t < nb) ? g_bsum[t] : 0;
    __syncthreads();
    if (t == 0) {
        int run = 0;
        for (int i = 0; i < nb; i++) { int v = sh[i]; sh[i] = run; run += v; }
    }
    __syncthreads();
    if (t < nb) g_bsum[t] = sh[t];
}

__global__ void scan3_kernel() {
    int i = blockIdx.x * blockDim.x + threadIdx.x;
    if (i == 0) g_rowptr[0] = 0;
    if (i < NN) g_rowptr[i + 1] += g_bsum[i >> 10];
}

__global__ void fill_adj_kernel(const int* __restrict__ w) {
    int e = blockIdx.x * blockDim.x + threadIdx.x;
    if (e >= ET) return;
    int s, d;
    if (e < NE) { s = edge_src(w, e); d = edge_dst(w, e); }
    else        { s = d = e - NE; }                       // self loop
    int pos = g_rowptr[d] + atomicAdd(&g_fill[d], 1);
    g_adj[pos] = s;
}

// ---------------- dense transform: Out = dinv[row] * (X @ W), 128x128 ----------------
// Classic tiled SGEMM: BM=BN=128, BK=8, 256 threads, 8x8 micro-tile per thread.
#define BM 128
#define BN 128
#define BK 8
#define TM 8
#define TN 8

__global__ void __launch_bounds__(256)
gemm128_kernel(const float* __restrict__ Xext, const float* __restrict__ W,
               int use_gh, int M) {
    const float* __restrict__ X = use_gh ? g_h : Xext;
    __shared__ float As[BK][BM];
    __shared__ float Bs[BK][BN];

    int tid = threadIdx.x;
    int block_row = blockIdx.x * BM;

    int arow  = tid >> 1;          // 0..127
    int acol4 = (tid & 1) * 4;     // 0 or 4
    int brow  = tid >> 5;          // 0..7
    int bcol4 = (tid & 31) * 4;    // 0..124

    int tx = tid & 15, ty = tid >> 4;
    float acc[TM][TN] = {};

    for (int k0 = 0; k0 < FDIM; k0 += BK) {
        float4 av = make_float4(0.f, 0.f, 0.f, 0.f);
        int gr = block_row + arow;
        if (gr < M)
            av = *(const float4*)(X + (size_t)gr * FDIM + k0 + acol4);
        As[acol4 + 0][arow] = av.x;
        As[acol4 + 1][arow] = av.y;
        As[acol4 + 2][arow] = av.z;
        As[acol4 + 3][arow] = av.w;

        float4 bv = *(const float4*)(W + (size_t)(k0 + brow) * BN + bcol4);
        *(float4*)&Bs[brow][bcol4] = bv;
        __syncthreads();

#pragma unroll
        for (int kk = 0; kk < BK; kk++) {
            float4 a0 = *(const float4*)&As[kk][ty * TM];
            float4 a1 = *(const float4*)&As[kk][ty * TM + 4];
            float4 b0 = *(const float4*)&Bs[kk][tx * TN];
            float4 b1 = *(const float4*)&Bs[kk][tx * TN + 4];
            float ar[TM] = {a0.x, a0.y, a0.z, a0.w, a1.x, a1.y, a1.z, a1.w};
            float br[TN] = {b0.x, b0.y, b0.z, b0.w, b1.x, b1.y, b1.z, b1.w};
#pragma unroll
            for (int i = 0; i < TM; i++)
#pragma unroll
                for (int j = 0; j < TN; j++)
                    acc[i][j] += ar[i] * br[j];
        }
        __syncthreads();
    }

#pragma unroll
    for (int i = 0; i < TM; i++) {
        int gr = block_row + ty * TM + i;
        if (gr >= M) continue;
        float s = g_dinv[gr];
#pragma unroll
        for (int j = 0; j < TN; j += 4) {
            float4 o;
            o.x = acc[i][j + 0] * s;
            o.y = acc[i][j + 1] * s;
            o.z = acc[i][j + 2] * s;
            o.w = acc[i][j + 3] * s;
            *(float4*)(g_t + (size_t)gr * FDIM + tx * TN + j) = o;
        }
    }
}

// ---------------- dense transform layer 3: g_l = dinv * (g_h @ W3), 128x40 ----------------
__global__ void __launch_bounds__(256)
gemm40_kernel(const float* __restrict__ W3, int M) {
    __shared__ float Wsh[FDIM * NCLS];   // 20 KB
    __shared__ float xbuf[8][FDIM];      // 4 KB

    int tid = threadIdx.x;
    for (int i = tid; i < FDIM * NCLS; i += 256) Wsh[i] = W3[i];
    __syncthreads();

    int warp = tid >> 5, lane = tid & 31;
    for (int row = blockIdx.x * 8 + warp; row < M; row += gridDim.x * 8) {
        float4 xv = *(const float4*)(g_h + (size_t)row * FDIM + lane * 4);
        *(float4*)&xbuf[warp][lane * 4] = xv;
        __syncwarp();

        float acc0 = 0.f, acc1 = 0.f;
#pragma unroll
        for (int k = 0; k < FDIM; k++) {
            float xk = xbuf[warp][k];
            acc0 += xk * Wsh[k * NCLS + lane];
            if (lane < 8) acc1 += xk * Wsh[k * NCLS + 32 + lane];
        }
        float dn = g_dinv[row];
        g_l[(size_t)row * NCLS + lane] = acc0 * dn;
        if (lane < 8) g_l[(size_t)row * NCLS + 32 + lane] = acc1 * dn;
        __syncwarp();
    }
}

// ---------------- aggregation, 128-wide: g_h[d] = act(dinv[d]*sum g_t[adj] + b) ----------------
__global__ void __launch_bounds__(256)
agg128_kernel(const float* __restrict__ bias, int relu) {
    int node = blockIdx.x * (blockDim.x >> 5) + (threadIdx.x >> 5);
    if (node >= NN) return;
    int lane = threadIdx.x & 31;

    int beg = g_rowptr[node], end = g_rowptr[node + 1];
    float4 acc = make_float4(0.f, 0.f, 0.f, 0.f);

    int e = beg;
    for (; e + 4 <= end; e += 4) {
        int s0 = __ldg(g_adj + e + 0);
        int s1 = __ldg(g_adj + e + 1);
        int s2 = __ldg(g_adj + e + 2);
        int s3 = __ldg(g_adj + e + 3);
        float4 v0 = __ldg((const float4*)(g_t + (size_t)s0 * FDIM) + lane);
        float4 v1 = __ldg((const float4*)(g_t + (size_t)s1 * FDIM) + lane);
        float4 v2 = __ldg((const float4*)(g_t + (size_t)s2 * FDIM) + lane);
        float4 v3 = __ldg((const float4*)(g_t + (size_t)s3 * FDIM) + lane);
        acc.x += (v0.x + v1.x) + (v2.x + v3.x);
        acc.y += (v0.y + v1.y) + (v2.y + v3.y);
        acc.z += (v0.z + v1.z) + (v2.z + v3.z);
        acc.w += (v0.w + v1.w) + (v2.w + v3.w);
    }
    for (; e < end; e++) {
        int s = __ldg(g_adj + e);
        float4 v = __ldg((const float4*)(g_t + (size_t)s * FDIM) + lane);
        acc.x += v.x; acc.y += v.y; acc.z += v.z; acc.w += v.w;
    }

    float dn = g_dinv[node];
    float4 b = __ldg((const float4*)bias + lane);
    float4 o;
    o.x = fmaf(acc.x, dn, b.x);
    o.y = fmaf(acc.y, dn, b.y);
    o.z = fmaf(acc.z, dn, b.z);
    o.w = fmaf(acc.w, dn, b.w);
    if (relu) {
        o.x = fmaxf(o.x, 0.f); o.y = fmaxf(o.y, 0.f);
        o.z = fmaxf(o.z, 0.f); o.w = fmaxf(o.w, 0.f);
    }
    *((float4*)(g_h + (size_t)node * FDIM) + lane) = o;
}

// ---------------- aggregation 40-wide + fused log_softmax ----------------
__global__ void __launch_bounds__(256)
agg40_lsm_kernel(const float* __restrict__ b3, float* __restrict__ out) {
    int node = blockIdx.x * (blockDim.x >> 5) + (threadIdx.x >> 5);
    if (node >= NN) return;
    int lane = threadIdx.x & 31;

    int beg = g_rowptr[node], end = g_rowptr[node + 1];
    float a0 = 0.f, a1 = 0.f;
#pragma unroll 4
    for (int e = beg; e < end; e++) {
        int s = __ldg(g_adj + e);
        const float* r = g_l + (size_t)s * NCLS;
        a0 += __ldg(r + lane);
        if (lane < 8) a1 += __ldg(r + 32 + lane);
    }

    float dn = g_dinv[node];
    float v0 = a0 * dn + __ldg(b3 + lane);
    float v1 = (lane < 8) ? (a1 * dn + __ldg(b3 + 32 + lane)) : -1e30f;

    float m = fmaxf(v0, v1);
#pragma unroll
    for (int off = 16; off; off >>= 1)
        m = fmaxf(m, __shfl_xor_sync(0xffffffffu, m, off));
    float s = __expf(v0 - m) + ((lane < 8) ? __expf(v1 - m) : 0.f);
#pragma unroll
    for (int off = 16; off; off >>= 1)
        s += __shfl_xor_sync(0xffffffffu, s, off);
    float L = __logf(s) + m;   // logsumexp

    out[(size_t)node * NCLS + lane] = v0 - L;
    if (lane < 8) out[(size_t)node * NCLS + 32 + lane] = v1 - L;
}

// ---------------- launch ----------------
extern "C" void kernel_launch(void* const* d_in, const int* in_sizes, int n_in,
                              void* d_out, int out_size) {
    const float* x  = (const float*)d_in[0];
    const int*   ei = (const int*)d_in[1];   // int32 view; dtype detected on device
    const float* W1 = (const float*)d_in[2];
    const float* b1 = (const float*)d_in[3];
    const float* W2 = (const float*)d_in[4];
    const float* b2 = (const float*)d_in[5];
    const float* W3 = (const float*)d_in[6];
    const float* b3 = (const float*)d_in[7];
    float* out = (float*)d_out;

    const int nbScan = (NN + SCAN_BLK - 1) / SCAN_BLK;      // 166
    const int gN   = (NN + 255) / 256;                      // 662
    const int gE   = (NE + 255) / 256;                      // 4557
    const int gET  = (ET + 255) / 256;                      // 5218
    const int gGmm = (NN + BM - 1) / BM;                    // 1324
    const int gAgg = (NN + 7) / 8;                          // 21168

    // --- graph preprocessing: degree, dinv, CSR by dst ---
    detect64_kernel<<<1, 256>>>(ei);
    init_deg_kernel<<<gN, 256>>>();
    count_deg_kernel<<<gE, 256>>>(ei);
    calc_dinv_kernel<<<gN, 256>>>();
    scan1_kernel<<<nbScan, SCAN_BLK>>>();
    scan2_kernel<<<1, 256>>>(nbScan);
    scan3_kernel<<<nbScan, SCAN_BLK>>>();
    fill_adj_kernel<<<gET, 256>>>(ei);

    // --- layer 1: t = dinv*(x@W1); h = relu(dinv*agg(t) + b1) ---
    gemm128_kernel<<<gGmm, 256>>>(x, W1, /*use_gh=*/0, NN);
    agg128_kernel<<<gAgg, 256>>>(b1, /*relu=*/1);

    // --- layer 2: t = dinv*(h@W2); h = dinv*agg(t) + b2 ---
    gemm128_kernel<<<gGmm, 256>>>(x, W2, /*use_gh=*/1, NN);
    agg128_kernel<<<gAgg, 256>>>(b2, /*relu=*/0);

    // --- layer 3: l = dinv*(h@W3); out = log_softmax(dinv*agg(l) + b3) ---
    gemm40_kernel<<<1184, 256>>>(W3, NN);
    agg40_lsm_kernel<<<gAgg, 256>>>(b3, out);

    (void)in_sizes; (void)n_in; (void)out_size;
}

// round 7
// speedup vs baseline: 1.3846x; 1.3846x over previous
#include <cuda_runtime.h>
#include <cuda_bf16.h>
#include <math.h>
#include <stdint.h>

// Problem constants (fixed by the dataset)
#define NN 169343            // nodes
#define NE 1166243           // edges
#define ET (NE + NN)         // edges + self loops = 1335586
#define FDIM 128
#define NCLS 40
#define NTILES ((NN + 127) / 128)   // 1324

#define ROWS_PAD 136         // bf16 elements per padded row (272 bytes)
#define ROWB 272             // bytes per padded row

// ---------------- device scratch (no cudaMalloc allowed) ----------------
__device__ int   g_is64;
__device__ int   g_deg[NN];
__device__ int   g_fill[NN];
__device__ int   g_rowptr[NN + 1];
__device__ int   g_bsum[256];
__device__ int   g_adj[ET];
__device__ float g_dinv[NN];
__device__ float g_t[(size_t)NN * FDIM]; // GEMM output (dinv[src]-scaled)
__device__ float g_h[(size_t)NN * FDIM]; // aggregated hidden
__device__ float g_l[(size_t)NN * NCLS]; // layer-3 GEMM output

// Pre-packed bf16 weight images ([n][k] layout, padded 136-elem rows, hi/lo split)
__device__ unsigned short g_Bh1[128 * ROWS_PAD], g_Bl1[128 * ROWS_PAD];
__device__ unsigned short g_Bh2[128 * ROWS_PAD], g_Bl2[128 * ROWS_PAD];
__device__ unsigned short g_Bh3[40 * ROWS_PAD],  g_Bl3[40 * ROWS_PAD];

// ---------------- PTX helpers (portable sm_80+ class only) ----------------
__device__ __forceinline__ uint32_t smem_u32(const void* p) {
    uint32_t a;
    asm("{ .reg .u64 t; cvta.to.shared.u64 t, %1; cvt.u32.u64 %0, t; }"
        : "=r"(a) : "l"(p));
    return a;
}

__device__ __forceinline__ void ldsm_x4(uint32_t& r0, uint32_t& r1,
                                        uint32_t& r2, uint32_t& r3, uint32_t addr) {
    asm volatile("ldmatrix.sync.aligned.m8n8.x4.shared.b16 {%0,%1,%2,%3}, [%4];"
                 : "=r"(r0), "=r"(r1), "=r"(r2), "=r"(r3) : "r"(addr));
}

__device__ __forceinline__ void ldsm_x2(uint32_t& r0, uint32_t& r1, uint32_t addr) {
    asm volatile("ldmatrix.sync.aligned.m8n8.x2.shared.b16 {%0,%1}, [%2];"
                 : "=r"(r0), "=r"(r1) : "r"(addr));
}

__device__ __forceinline__ void mma_bf16(float& d0, float& d1, float& d2, float& d3,
                                         uint32_t a0, uint32_t a1, uint32_t a2, uint32_t a3,
                                         uint32_t b0, uint32_t b1) {
    asm volatile(
        "mma.sync.aligned.m16n8k16.row.col.f32.bf16.bf16.f32 "
        "{%0,%1,%2,%3}, {%4,%5,%6,%7}, {%8,%9}, {%0,%1,%2,%3};"
        : "+f"(d0), "+f"(d1), "+f"(d2), "+f"(d3)
        : "r"(a0), "r"(a1), "r"(a2), "r"(a3), "r"(b0), "r"(b1));
}

// ---------------- dtype detection for edge_index ----------------
__global__ void detect64_kernel(const int* __restrict__ w) {
    __shared__ int bad;
    if (threadIdx.x == 0) bad = 0;
    __syncthreads();
    for (int i = threadIdx.x; i < 1024; i += blockDim.x)
        if (w[2 * i + 1] != 0) atomicAdd(&bad, 1);
    __syncthreads();
    if (threadIdx.x == 0) g_is64 = (bad == 0) ? 1 : 0;
}

__device__ __forceinline__ int edge_src(const int* w, int e) {
    return g_is64 ? w[2 * e] : w[e];
}
__device__ __forceinline__ int edge_dst(const int* w, int e) {
    return g_is64 ? w[2 * (NE + e)] : w[NE + e];
}

// ---------------- preprocessing ----------------
__global__ void init_deg_kernel() {
    int i = blockIdx.x * blockDim.x + threadIdx.x;
    if (i < NN) { g_deg[i] = 1; g_fill[i] = 0; }
}

__global__ void count_deg_kernel(const int* __restrict__ w) {
    int e = blockIdx.x * blockDim.x + threadIdx.x;
    if (e >= NE) return;
    atomicAdd(&g_deg[edge_dst(w, e)], 1);
}

__global__ void calc_dinv_kernel() {
    int i = blockIdx.x * blockDim.x + threadIdx.x;
    if (i < NN) g_dinv[i] = rsqrtf((float)g_deg[i]);
}

#define SCAN_BLK 1024
__global__ void scan1_kernel() {
    __shared__ int sh[SCAN_BLK];
    int i = blockIdx.x * SCAN_BLK + threadIdx.x;
    int v = (i < NN) ? g_deg[i] : 0;
    sh[threadIdx.x] = v;
    __syncthreads();
    for (int off = 1; off < SCAN_BLK; off <<= 1) {
        int add = (threadIdx.x >= off) ? sh[threadIdx.x - off] : 0;
        __syncthreads();
        sh[threadIdx.x] += add;
        __syncthreads();
    }
    if (i < NN) g_rowptr[i + 1] = sh[threadIdx.x];
    if (threadIdx.x == SCAN_BLK - 1) g_bsum[blockIdx.x] = sh[threadIdx.x];
}

__global__ void scan2_kernel(int nb) {
    __shared__ int sh[256];
    int t = threadIdx.x;
    sh[t] = (t < nb) ? g_bsum[t] : 0;
    __syncthreads();
    if (t == 0) {
        int run = 0;
        for (int i = 0; i < nb; i++) { int v = sh[i]; sh[i] = run; run += v; }
    }
    __syncthreads();
    if (t < nb) g_bsum[t] = sh[t];
}

__global__ void scan3_kernel() {
    int i = blockIdx.x * blockDim.x + threadIdx.x;
    if (i == 0) g_rowptr[0] = 0;
    if (i < NN) g_rowptr[i + 1] += g_bsum[i >> 10];
}

__global__ void fill_adj_kernel(const int* __restrict__ w) {
    int e = blockIdx.x * blockDim.x + threadIdx.x;
    if (e >= ET) return;
    int s, d;
    if (e < NE) { s = edge_src(w, e); d = edge_dst(w, e); }
    else        { s = d = e - NE; }
    int pos = g_rowptr[d] + atomicAdd(&g_fill[d], 1);
    g_adj[pos] = s;
}

// ---------------- weight pre-pack: W[k][n] -> B[n][k] bf16 hi/lo, padded rows ----------------
__global__ void pack_w_kernel(const float* __restrict__ W, int Nout, int sel) {
    int idx = blockIdx.x * blockDim.x + threadIdx.x;
    if (idx >= Nout * 128) return;
    int n = idx >> 7, k = idx & 127;
    float v = W[k * Nout + n];
    unsigned short h; asm("cvt.rn.bf16.f32 %0, %1;" : "=h"(h) : "f"(v));
    float hf = __uint_as_float(((unsigned)h) << 16);
    float rres = v - hf;
    unsigned short l; asm("cvt.rn.bf16.f32 %0, %1;" : "=h"(l) : "f"(rres));

    unsigned short* bh = (sel == 0) ? g_Bh1 : (sel == 1) ? g_Bh2 : g_Bh3;
    unsigned short* bl = (sel == 0) ? g_Bl1 : (sel == 1) ? g_Bl2 : g_Bl3;
    bh[n * ROWS_PAD + k] = h;
    bl[n * ROWS_PAD + k] = l;
}

// ---------------- tensor-core GEMM (mma.sync bf16 x3 split) ----------------
// out = dinv[row] * (A @ W); A: [M][128] fp32, W packed as B[n][k] bf16 hi/lo.
// NOUT = 128 (out -> g_t, stride 128) or 40 (out -> g_l, stride 40).
// Persistent CTAs; B resident in smem; 256 threads.
template<int NOUT>
__global__ void __launch_bounds__(256, 1)
gemm_mma_kernel(const float* __restrict__ Aext, int use_gh, int sel, int M) {
    extern __shared__ __align__(16) char smem[];
    const int AHI = 0;
    const int ALO = 128 * ROWB;              // 34816
    const int BHI = 2 * 128 * ROWB;          // 69632
    const int BBYTES = NOUT * ROWB;
    const int BLO = BHI + BBYTES;

    const float* __restrict__ A = use_gh ? g_h : Aext;
    float* __restrict__ out = (NOUT == 128) ? g_t : g_l;
    const int LDOUT = (NOUT == 128) ? 128 : NCLS;
    const char* bh = (sel == 0) ? (const char*)g_Bh1 : (sel == 1) ? (const char*)g_Bh2 : (const char*)g_Bh3;
    const char* bl = (sel == 0) ? (const char*)g_Bl1 : (sel == 1) ? (const char*)g_Bl2 : (const char*)g_Bl3;

    const uint32_t sb = smem_u32(smem);
    const int tid = threadIdx.x, wid = tid >> 5, lane = tid & 31;

    // ---- copy pre-packed B images into smem (layouts identical) ----
    for (int i = tid; i < BBYTES / 16; i += 256) {
        ((float4*)(smem + BHI))[i] = ((const float4*)bh)[i];
        ((float4*)(smem + BLO))[i] = ((const float4*)bl)[i];
    }

    // warp tiling
    const int MT = (NOUT == 128) ? 2 : 1;    // 16-row m-tiles per warp
    const int NT = (NOUT == 128) ? 8 : 5;    // 8-col n-tiles per warp
    const int m0 = (NOUT == 128) ? (wid & 3) * 32 : wid * 16;
    const int n0 = (NOUT == 128) ? (wid >> 2) * 64 : 0;

    // ldmatrix lane addresses (constant per thread)
    const int a_r = lane & 15, a_kh = lane >> 4;          // A: row-in-tile, k-half
    const int b_r = lane & 7,  b_kh = (lane >> 3) & 1;    // B: row-in-tile, k-half

    for (int tile = blockIdx.x; tile < NTILES; tile += gridDim.x) {
        const int row0 = tile * 128;

        // ---- load A tile, split fp32 -> bf16 hi/lo into smem ----
#pragma unroll
        for (int i = 0; i < 16; i++) {
            int idx = tid + i * 256;          // 4096 float4 slots
            int r  = idx >> 5;
            int c4 = (idx & 31) << 2;
            int grow = row0 + r;
            float4 v = make_float4(0.f, 0.f, 0.f, 0.f);
            if (grow < M) v = *(const float4*)(A + (size_t)grow * FDIM + c4);

            unsigned short h0, h1, h2, h3;
            asm("cvt.rn.bf16.f32 %0, %1;" : "=h"(h0) : "f"(v.x));
            asm("cvt.rn.bf16.f32 %0, %1;" : "=h"(h1) : "f"(v.y));
            asm("cvt.rn.bf16.f32 %0, %1;" : "=h"(h2) : "f"(v.z));
            asm("cvt.rn.bf16.f32 %0, %1;" : "=h"(h3) : "f"(v.w));
            float r0 = v.x - __uint_as_float((unsigned)h0 << 16);
            float r1 = v.y - __uint_as_float((unsigned)h1 << 16);
            float r2 = v.z - __uint_as_float((unsigned)h2 << 16);
            float r3 = v.w - __uint_as_float((unsigned)h3 << 16);
            uint32_t hi01 = (uint32_t)h0 | ((uint32_t)h1 << 16);
            uint32_t hi23 = (uint32_t)h2 | ((uint32_t)h3 << 16);
            uint32_t lo01, lo23;
            asm("cvt.rn.bf16x2.f32 %0, %1, %2;" : "=r"(lo01) : "f"(r1), "f"(r0));
            asm("cvt.rn.bf16x2.f32 %0, %1, %2;" : "=r"(lo23) : "f"(r3), "f"(r2));

            int off = r * ROWB + c4 * 2;
            *(uint2*)(smem + AHI + off) = make_uint2(hi01, hi23);
            *(uint2*)(smem + ALO + off) = make_uint2(lo01, lo23);
        }
        __syncthreads();

        // ---- K loop: 8 steps of k16, 3 split combos each ----
        float acc[MT][NT][4];
#pragma unroll
        for (int mt = 0; mt < MT; mt++)
#pragma unroll
            for (int nt = 0; nt < NT; nt++)
#pragma unroll
                for (int j = 0; j < 4; j++) acc[mt][nt][j] = 0.f;

#pragma unroll
        for (int ks = 0; ks < 8; ks++) {
            const int k0 = ks * 16;
            uint32_t ah[MT][4], al[MT][4];
#pragma unroll
            for (int mt = 0; mt < MT; mt++) {
                uint32_t aoff = (uint32_t)((m0 + mt * 16 + a_r) * ROWB
                                           + (k0 + a_kh * 8) * 2);
                ldsm_x4(ah[mt][0], ah[mt][1], ah[mt][2], ah[mt][3], sb + AHI + aoff);
                ldsm_x4(al[mt][0], al[mt][1], al[mt][2], al[mt][3], sb + ALO + aoff);
            }
            uint32_t bhf[NT][2], blf[NT][2];
#pragma unroll
            for (int nt = 0; nt < NT; nt++) {
                uint32_t boff = (uint32_t)((n0 + nt * 8 + b_r) * ROWB
                                           + (k0 + b_kh * 8) * 2);
                ldsm_x2(bhf[nt][0], bhf[nt][1], sb + BHI + boff);
                ldsm_x2(blf[nt][0], blf[nt][1], sb + BLO + boff);
            }
#pragma unroll
            for (int mt = 0; mt < MT; mt++)
#pragma unroll
                for (int nt = 0; nt < NT; nt++) {
                    mma_bf16(acc[mt][nt][0], acc[mt][nt][1], acc[mt][nt][2], acc[mt][nt][3],
                             ah[mt][0], ah[mt][1], ah[mt][2], ah[mt][3],
                             bhf[nt][0], bhf[nt][1]);
                    mma_bf16(acc[mt][nt][0], acc[mt][nt][1], acc[mt][nt][2], acc[mt][nt][3],
                             ah[mt][0], ah[mt][1], ah[mt][2], ah[mt][3],
                             blf[nt][0], blf[nt][1]);
                    mma_bf16(acc[mt][nt][0], acc[mt][nt][1], acc[mt][nt][2], acc[mt][nt][3],
                             al[mt][0], al[mt][1], al[mt][2], al[mt][3],
                             bhf[nt][0], bhf[nt][1]);
                }
        }

        // ---- epilogue: scale by dinv[row], write out ----
        const int qr = lane >> 2, qc = (lane & 3) * 2;
#pragma unroll
        for (int mt = 0; mt < MT; mt++) {
            int r_a = row0 + m0 + mt * 16 + qr;
            int r_b = r_a + 8;
            float dna = (r_a < M) ? g_dinv[r_a] : 0.f;
            float dnb = (r_b < M) ? g_dinv[r_b] : 0.f;
#pragma unroll
            for (int nt = 0; nt < NT; nt++) {
                int col = n0 + nt * 8 + qc;
                if (r_a < M) {
                    float2 o = make_float2(acc[mt][nt][0] * dna, acc[mt][nt][1] * dna);
                    *(float2*)(out + (size_t)r_a * LDOUT + col) = o;
                }
                if (r_b < M) {
                    float2 o = make_float2(acc[mt][nt][2] * dnb, acc[mt][nt][3] * dnb);
                    *(float2*)(out + (size_t)r_b * LDOUT + col) = o;
                }
            }
        }
        __syncthreads();   // protect smem A before next tile overwrites it
    }
}

// ---------------- aggregation, 128-wide ----------------
__global__ void __launch_bounds__(256)
agg128_kernel(const float* __restrict__ bias, int relu) {
    int node = blockIdx.x * (blockDim.x >> 5) + (threadIdx.x >> 5);
    if (node >= NN) return;
    int lane = threadIdx.x & 31;

    int beg = g_rowptr[node], end = g_rowptr[node + 1];
    float4 acc = make_float4(0.f, 0.f, 0.f, 0.f);

    int e = beg;
    for (; e + 4 <= end; e += 4) {
        int s0 = __ldg(g_adj + e + 0);
        int s1 = __ldg(g_adj + e + 1);
        int s2 = __ldg(g_adj + e + 2);
        int s3 = __ldg(g_adj + e + 3);
        float4 v0 = __ldg((const float4*)(g_t + (size_t)s0 * FDIM) + lane);
        float4 v1 = __ldg((const float4*)(g_t + (size_t)s1 * FDIM) + lane);
        float4 v2 = __ldg((const float4*)(g_t + (size_t)s2 * FDIM) + lane);
        float4 v3 = __ldg((const float4*)(g_t + (size_t)s3 * FDIM) + lane);
        acc.x += (v0.x + v1.x) + (v2.x + v3.x);
        acc.y += (v0.y + v1.y) + (v2.y + v3.y);
        acc.z += (v0.z + v1.z) + (v2.z + v3.z);
        acc.w += (v0.w + v1.w) + (v2.w + v3.w);
    }
    for (; e < end; e++) {
        int s = __ldg(g_adj + e);
        float4 v = __ldg((const float4*)(g_t + (size_t)s * FDIM) + lane);
        acc.x += v.x; acc.y += v.y; acc.z += v.z; acc.w += v.w;
    }

    float dn = g_dinv[node];
    float4 b = __ldg((const float4*)bias + lane);
    float4 o;
    o.x = fmaf(acc.x, dn, b.x);
    o.y = fmaf(acc.y, dn, b.y);
    o.z = fmaf(acc.z, dn, b.z);
    o.w = fmaf(acc.w, dn, b.w);
    if (relu) {
        o.x = fmaxf(o.x, 0.f); o.y = fmaxf(o.y, 0.f);
        o.z = fmaxf(o.z, 0.f); o.w = fmaxf(o.w, 0.f);
    }
    *((float4*)(g_h + (size_t)node * FDIM) + lane) = o;
}

// ---------------- aggregation 40-wide + fused log_softmax ----------------
__global__ void __launch_bounds__(256)
agg40_lsm_kernel(const float* __restrict__ b3, float* __restrict__ out) {
    int node = blockIdx.x * (blockDim.x >> 5) + (threadIdx.x >> 5);
    if (node >= NN) return;
    int lane = threadIdx.x & 31;

    int beg = g_rowptr[node], end = g_rowptr[node + 1];
    float a0 = 0.f, a1 = 0.f;
#pragma unroll 4
    for (int e = beg; e < end; e++) {
        int s = __ldg(g_adj + e);
        const float* r = g_l + (size_t)s * NCLS;
        a0 += __ldg(r + lane);
        if (lane < 8) a1 += __ldg(r + 32 + lane);
    }

    float dn = g_dinv[node];
    float v0 = a0 * dn + __ldg(b3 + lane);
    float v1 = (lane < 8) ? (a1 * dn + __ldg(b3 + 32 + lane)) : -1e30f;

    float m = fmaxf(v0, v1);
#pragma unroll
    for (int off = 16; off; off >>= 1)
        m = fmaxf(m, __shfl_xor_sync(0xffffffffu, m, off));
    float s = __expf(v0 - m) + ((lane < 8) ? __expf(v1 - m) : 0.f);
#pragma unroll
    for (int off = 16; off; off >>= 1)
        s += __shfl_xor_sync(0xffffffffu, s, off);
    float L = __logf(s) + m;

    out[(size_t)node * NCLS + lane] = v0 - L;
    if (lane < 8) out[(size_t)node * NCLS + 32 + lane] = v1 - L;
}

// ---------------- launch ----------------
extern "C" void kernel_launch(void* const* d_in, const int* in_sizes, int n_in,
                              void* d_out, int out_size) {
    const float* x  = (const float*)d_in[0];
    const int*   ei = (const int*)d_in[1];
    const float* W1 = (const float*)d_in[2];
    const float* b1 = (const float*)d_in[3];
    const float* W2 = (const float*)d_in[4];
    const float* b2 = (const float*)d_in[5];
    const float* W3 = (const float*)d_in[6];
    const float* b3 = (const float*)d_in[7];
    float* out = (float*)d_out;

    const int nbScan = (NN + SCAN_BLK - 1) / SCAN_BLK;
    const int gN   = (NN + 255) / 256;
    const int gE   = (NE + 255) / 256;
    const int gET  = (ET + 255) / 256;
    const int gAgg = (NN + 7) / 8;

    const int SMEM128 = 2 * 128 * ROWB + 2 * 128 * ROWB;   // 139264
    const int SMEM40  = 2 * 128 * ROWB + 2 * 40 * ROWB;    //  91392
    cudaFuncSetAttribute(gemm_mma_kernel<128>,
                         cudaFuncAttributeMaxDynamicSharedMemorySize, SMEM128);
    cudaFuncSetAttribute(gemm_mma_kernel<40>,
                         cudaFuncAttributeMaxDynamicSharedMemorySize, SMEM40);

    // --- graph preprocessing ---
    detect64_kernel<<<1, 256>>>(ei);
    init_deg_kernel<<<gN, 256>>>();
    count_deg_kernel<<<gE, 256>>>(ei);
    calc_dinv_kernel<<<gN, 256>>>();
    scan1_kernel<<<nbScan, SCAN_BLK>>>();
    scan2_kernel<<<1, 256>>>(nbScan);
    scan3_kernel<<<nbScan, SCAN_BLK>>>();
    fill_adj_kernel<<<gET, 256>>>(ei);

    // --- weight pre-pack (bf16 hi/lo, padded [n][k] image) ---
    pack_w_kernel<<<(128 * 128 + 255) / 256, 256>>>(W1, 128, 0);
    pack_w_kernel<<<(128 * 128 + 255) / 256, 256>>>(W2, 128, 1);
    pack_w_kernel<<<(40 * 128 + 255) / 256, 256>>>(W3, NCLS, 2);

    // --- layer 1 ---
    gemm_mma_kernel<128><<<148, 256, SMEM128>>>(x, 0, 0, NN);
    agg128_kernel<<<gAgg, 256>>>(b1, 1);

    // --- layer 2 ---
    gemm_mma_kernel<128><<<148, 256, SMEM128>>>(x, 1, 1, NN);
    agg128_kernel<<<gAgg, 256>>>(b2, 0);

    // --- layer 3 + log_softmax ---
    gemm_mma_kernel<40><<<148, 256, SMEM40>>>(x, 1, 2, NN);
    agg40_lsm_kernel<<<gAgg, 256>>>(b3, out);

    (void)in_sizes; (void)n_in; (void)out_size;
}

// round 8
// speedup vs baseline: 1.4744x; 1.0649x over previous
#include <cuda_runtime.h>
#include <cuda_bf16.h>
#include <math.h>
#include <stdint.h>

// Problem constants (fixed by the dataset)
#define NN 169343            // nodes
#define NE 1166243           // edges
#define ET (NE + NN)         // edges + self loops = 1335586
#define FDIM 128
#define NCLS 40
#define NTILES ((NN + 127) / 128)   // 1324

#define ROWS_PAD 136         // bf16 elements per padded row
#define ROWB 272             // bytes per padded row

// ---------------- device scratch (no cudaMalloc allowed) ----------------
__device__ int   g_is64;
__device__ int   g_deg[NN];
__device__ int   g_fill[NN];
__device__ int   g_rowptr[NN + 1];
__device__ int   g_bsum[256];
__device__ int   g_adj[ET];
__device__ float g_dinv[NN];
__device__ float g_ta[(size_t)NN * FDIM]; // layer-1 GEMM output t1
__device__ float g_tb[(size_t)NN * FDIM]; // layer-2 GEMM output t2
__device__ float g_l[(size_t)NN * NCLS];  // layer-3 GEMM output

// Pre-packed bf16 weight images ([n][k], padded rows, hi/lo split)
__device__ unsigned short g_Bh1[128 * ROWS_PAD], g_Bl1[128 * ROWS_PAD];
__device__ unsigned short g_Bh2[128 * ROWS_PAD], g_Bl2[128 * ROWS_PAD];
__device__ unsigned short g_Bh3[40 * ROWS_PAD],  g_Bl3[40 * ROWS_PAD];

// ---------------- PTX helpers (portable sm_80+ class only) ----------------
__device__ __forceinline__ uint32_t smem_u32(const void* p) {
    uint32_t a;
    asm("{ .reg .u64 t; cvta.to.shared.u64 t, %1; cvt.u32.u64 %0, t; }"
        : "=r"(a) : "l"(p));
    return a;
}

__device__ __forceinline__ void ldsm_x4(uint32_t& r0, uint32_t& r1,
                                        uint32_t& r2, uint32_t& r3, uint32_t addr) {
    asm volatile("ldmatrix.sync.aligned.m8n8.x4.shared.b16 {%0,%1,%2,%3}, [%4];"
                 : "=r"(r0), "=r"(r1), "=r"(r2), "=r"(r3) : "r"(addr));
}

__device__ __forceinline__ void ldsm_x2(uint32_t& r0, uint32_t& r1, uint32_t addr) {
    asm volatile("ldmatrix.sync.aligned.m8n8.x2.shared.b16 {%0,%1}, [%2];"
                 : "=r"(r0), "=r"(r1) : "r"(addr));
}

__device__ __forceinline__ void mma_bf16(float& d0, float& d1, float& d2, float& d3,
                                         uint32_t a0, uint32_t a1, uint32_t a2, uint32_t a3,
                                         uint32_t b0, uint32_t b1) {
    asm volatile(
        "mma.sync.aligned.m16n8k16.row.col.f32.bf16.bf16.f32 "
        "{%0,%1,%2,%3}, {%4,%5,%6,%7}, {%8,%9}, {%0,%1,%2,%3};"
        : "+f"(d0), "+f"(d1), "+f"(d2), "+f"(d3)
        : "r"(a0), "r"(a1), "r"(a2), "r"(a3), "r"(b0), "r"(b1));
}

// split fp32 float4 -> bf16 hi/lo packed uint2 pair
__device__ __forceinline__ void split4(const float4& v, uint2& hi, uint2& lo) {
    unsigned short h0, h1, h2, h3;
    asm("cvt.rn.bf16.f32 %0, %1;" : "=h"(h0) : "f"(v.x));
    asm("cvt.rn.bf16.f32 %0, %1;" : "=h"(h1) : "f"(v.y));
    asm("cvt.rn.bf16.f32 %0, %1;" : "=h"(h2) : "f"(v.z));
    asm("cvt.rn.bf16.f32 %0, %1;" : "=h"(h3) : "f"(v.w));
    float r0 = v.x - __uint_as_float((unsigned)h0 << 16);
    float r1 = v.y - __uint_as_float((unsigned)h1 << 16);
    float r2 = v.z - __uint_as_float((unsigned)h2 << 16);
    float r3 = v.w - __uint_as_float((unsigned)h3 << 16);
    hi.x = (uint32_t)h0 | ((uint32_t)h1 << 16);
    hi.y = (uint32_t)h2 | ((uint32_t)h3 << 16);
    asm("cvt.rn.bf16x2.f32 %0, %1, %2;" : "=r"(lo.x) : "f"(r1), "f"(r0));
    asm("cvt.rn.bf16x2.f32 %0, %1, %2;" : "=r"(lo.y) : "f"(r3), "f"(r2));
}

// ---------------- dtype detection for edge_index ----------------
__global__ void detect64_kernel(const int* __restrict__ w) {
    __shared__ int bad;
    if (threadIdx.x == 0) bad = 0;
    __syncthreads();
    for (int i = threadIdx.x; i < 1024; i += blockDim.x)
        if (w[2 * i + 1] != 0) atomicAdd(&bad, 1);
    __syncthreads();
    if (threadIdx.x == 0) g_is64 = (bad == 0) ? 1 : 0;
}

__device__ __forceinline__ int edge_src(const int* w, int e) {
    return g_is64 ? w[2 * e] : w[e];
}
__device__ __forceinline__ int edge_dst(const int* w, int e) {
    return g_is64 ? w[2 * (NE + e)] : w[NE + e];
}

// ---------------- preprocessing ----------------
__global__ void init_deg_kernel() {
    int i = blockIdx.x * blockDim.x + threadIdx.x;
    if (i < NN) { g_deg[i] = 1; g_fill[i] = 0; }
}

__global__ void count_deg_kernel(const int* __restrict__ w) {
    int e = blockIdx.x * blockDim.x + threadIdx.x;
    if (e >= NE) return;
    atomicAdd(&g_deg[edge_dst(w, e)], 1);
}

__global__ void calc_dinv_kernel() {
    int i = blockIdx.x * blockDim.x + threadIdx.x;
    if (i < NN) g_dinv[i] = rsqrtf((float)g_deg[i]);
}

#define SCAN_BLK 1024
__global__ void scan1_kernel() {
    __shared__ int sh[SCAN_BLK];
    int i = blockIdx.x * SCAN_BLK + threadIdx.x;
    int v = (i < NN) ? g_deg[i] : 0;
    sh[threadIdx.x] = v;
    __syncthreads();
    for (int off = 1; off < SCAN_BLK; off <<= 1) {
        int add = (threadIdx.x >= off) ? sh[threadIdx.x - off] : 0;
        __syncthreads();
        sh[threadIdx.x] += add;
        __syncthreads();
    }
    if (i < NN) g_rowptr[i + 1] = sh[threadIdx.x];
    if (threadIdx.x == SCAN_BLK - 1) g_bsum[blockIdx.x] = sh[threadIdx.x];
}

__global__ void scan2_kernel(int nb) {
    __shared__ int sh[256];
    int t = threadIdx.x;
    sh[t] = (t < nb) ? g_bsum[t] : 0;
    __syncthreads();
    if (t == 0) {
        int run = 0;
        for (int i = 0; i < nb; i++) { int v = sh[i]; sh[i] = run; run += v; }
    }
    __syncthreads();
    if (t < nb) g_bsum[t] = sh[t];
}

__global__ void scan3_kernel() {
    int i = blockIdx.x * blockDim.x + threadIdx.x;
    if (i == 0) g_rowptr[0] = 0;
    if (i < NN) g_rowptr[i + 1] += g_bsum[i >> 10];
}

__global__ void fill_adj_kernel(const int* __restrict__ w) {
    int e = blockIdx.x * blockDim.x + threadIdx.x;
    if (e >= ET) return;
    int s, d;
    if (e < NE) { s = edge_src(w, e); d = edge_dst(w, e); }
    else        { s = d = e - NE; }
    int pos = g_rowptr[d] + atomicAdd(&g_fill[d], 1);
    g_adj[pos] = s;
}

// ---------------- weight pre-pack: W[k][n] -> B[n][k] bf16 hi/lo ----------------
__global__ void pack_w_kernel(const float* __restrict__ W, int Nout, int sel) {
    int idx = blockIdx.x * blockDim.x + threadIdx.x;
    if (idx >= Nout * 128) return;
    int n = idx >> 7, k = idx & 127;
    float v = W[k * Nout + n];
    unsigned short h; asm("cvt.rn.bf16.f32 %0, %1;" : "=h"(h) : "f"(v));
    float hf = __uint_as_float(((unsigned)h) << 16);
    float rres = v - hf;
    unsigned short l; asm("cvt.rn.bf16.f32 %0, %1;" : "=h"(l) : "f"(rres));

    unsigned short* bh = (sel == 0) ? g_Bh1 : (sel == 1) ? g_Bh2 : g_Bh3;
    unsigned short* bl = (sel == 0) ? g_Bl1 : (sel == 1) ? g_Bl2 : g_Bl3;
    bh[n * ROWS_PAD + k] = h;
    bl[n * ROWS_PAD + k] = l;
}

// smem layout: AHI @0 (34816), ALO @34816, BHI @69632, BLO @69632+BBYTES
#define AHI_OFF 0
#define ALO_OFF 34816
#define BHI_OFF 69632

// ---------------- GEMM1: g_ta = dinv[row] * (x @ W1) ----------------
__global__ void __launch_bounds__(512, 1)
gemm1_kernel(const float* __restrict__ A, int M) {
    extern __shared__ __align__(16) char smem[];
    const int BLO_OFF = BHI_OFF + 128 * ROWB;
    const uint32_t sb = smem_u32(smem);
    const int tid = threadIdx.x, wid = tid >> 5, lane = tid & 31;

    for (int i = tid; i < (128 * ROWB) / 16; i += 512) {
        ((float4*)(smem + BHI_OFF))[i] = ((const float4*)g_Bh1)[i];
        ((float4*)(smem + BLO_OFF))[i] = ((const float4*)g_Bl1)[i];
    }

    const int m0 = (wid & 7) * 16;
    const int n0 = (wid >> 3) * 64;
    const int a_r = lane & 15, a_kh = lane >> 4;
    const int b_r = lane & 7,  b_kh = (lane >> 3) & 1;

    for (int tile = blockIdx.x; tile < NTILES; tile += gridDim.x) {
        const int row0 = tile * 128;

#pragma unroll
        for (int i = 0; i < 8; i++) {
            int idx = tid + i * 512;
            int r = idx >> 5, c4 = (idx & 31) << 2;
            int grow = row0 + r;
            float4 v = make_float4(0.f, 0.f, 0.f, 0.f);
            if (grow < M) v = *(const float4*)(A + (size_t)grow * FDIM + c4);
            uint2 hi, lo; split4(v, hi, lo);
            int off = r * ROWB + c4 * 2;
            *(uint2*)(smem + AHI_OFF + off) = hi;
            *(uint2*)(smem + ALO_OFF + off) = lo;
        }
        __syncthreads();

        float acc[8][4];
#pragma unroll
        for (int nt = 0; nt < 8; nt++)
#pragma unroll
            for (int j = 0; j < 4; j++) acc[nt][j] = 0.f;

#pragma unroll
        for (int ks = 0; ks < 8; ks++) {
            const int k0 = ks * 16;
            uint32_t ah[4], al[4];
            uint32_t aoff = (uint32_t)((m0 + a_r) * ROWB + (k0 + a_kh * 8) * 2);
            ldsm_x4(ah[0], ah[1], ah[2], ah[3], sb + AHI_OFF + aoff);
            ldsm_x4(al[0], al[1], al[2], al[3], sb + ALO_OFF + aoff);
#pragma unroll
            for (int nt = 0; nt < 8; nt++) {
                uint32_t boff = (uint32_t)((n0 + nt * 8 + b_r) * ROWB + (k0 + b_kh * 8) * 2);
                uint32_t bh0, bh1, bl0, bl1;
                ldsm_x2(bh0, bh1, sb + BHI_OFF + boff);
                ldsm_x2(bl0, bl1, sb + BLO_OFF + boff);
                mma_bf16(acc[nt][0], acc[nt][1], acc[nt][2], acc[nt][3],
                         ah[0], ah[1], ah[2], ah[3], bh0, bh1);
                mma_bf16(acc[nt][0], acc[nt][1], acc[nt][2], acc[nt][3],
                         ah[0], ah[1], ah[2], ah[3], bl0, bl1);
                mma_bf16(acc[nt][0], acc[nt][1], acc[nt][2], acc[nt][3],
                         al[0], al[1], al[2], al[3], bh0, bh1);
            }
        }
        __syncthreads();

        const int qr = lane >> 2, qc = (lane & 3) * 2;
        int r_a = row0 + m0 + qr, r_b = r_a + 8;
        float dna = (r_a < M) ? g_dinv[r_a] : 0.f;
        float dnb = (r_b < M) ? g_dinv[r_b] : 0.f;
#pragma unroll
        for (int nt = 0; nt < 8; nt++) {
            int col = n0 + nt * 8 + qc;
            if (r_a < M)
                *(float2*)(g_ta + (size_t)r_a * FDIM + col) =
                    make_float2(acc[nt][0] * dna, acc[nt][1] * dna);
            if (r_b < M)
                *(float2*)(g_ta + (size_t)r_b * FDIM + col) =
                    make_float2(acc[nt][2] * dnb, acc[nt][3] * dnb);
        }
    }
}

// ---------------- fused: agg(src) -> bias/relu -> @W -> dinv -> dst ----------------
template<int NOUT, int SRCSEL>
__global__ void __launch_bounds__(512, 1)
fused_agg_gemm_kernel(const float* __restrict__ bias, int relu, int M) {
    extern __shared__ __align__(16) char smem[];
    const int BBYTES = NOUT * ROWB;
    const int BLO_OFF = BHI_OFF + BBYTES;
    const uint32_t sb = smem_u32(smem);
    const int tid = threadIdx.x, wid = tid >> 5, lane = tid & 31;

    const float* __restrict__ src = SRCSEL ? g_tb : g_ta;
    float* __restrict__ out = (NOUT == 128) ? g_tb : g_l;
    const int LDOUT = (NOUT == 128) ? FDIM : NCLS;
    const unsigned short* bh = SRCSEL ? g_Bh3 : g_Bh2;
    const unsigned short* bl = SRCSEL ? g_Bl3 : g_Bl2;

    for (int i = tid; i < BBYTES / 16; i += 512) {
        ((float4*)(smem + BHI_OFF))[i] = ((const float4*)bh)[i];
        ((float4*)(smem + BLO_OFF))[i] = ((const float4*)bl)[i];
    }

    const int m0 = (wid & 7) * 16;
    const int nhalf = wid >> 3;
    const int n0 = (NOUT == 128) ? nhalf * 64 : nhalf * 24;
    const int NT = (NOUT == 128) ? 8 : (nhalf ? 2 : 3);
    const int a_r = lane & 15, a_kh = lane >> 4;
    const int b_r = lane & 7,  b_kh = (lane >> 3) & 1;

    const float4 bv = __ldg((const float4*)bias + lane);

    for (int tile = blockIdx.x; tile < NTILES; tile += gridDim.x) {
        const int row0 = tile * 128;

        // ---- gather phase: warp w -> rows w*8 .. w*8+7 of this tile ----
#pragma unroll
        for (int r8 = 0; r8 < 8; r8++) {
            int lr = wid * 8 + r8;
            int node = row0 + lr;
            float4 acc = make_float4(0.f, 0.f, 0.f, 0.f);
            if (node < M) {
                int beg = g_rowptr[node], end = g_rowptr[node + 1];
                int e = beg;
                for (; e + 4 <= end; e += 4) {
                    int s0 = __ldg(g_adj + e + 0);
                    int s1 = __ldg(g_adj + e + 1);
                    int s2 = __ldg(g_adj + e + 2);
                    int s3 = __ldg(g_adj + e + 3);
                    float4 v0 = __ldg((const float4*)(src + (size_t)s0 * FDIM) + lane);
                    float4 v1 = __ldg((const float4*)(src + (size_t)s1 * FDIM) + lane);
                    float4 v2 = __ldg((const float4*)(src + (size_t)s2 * FDIM) + lane);
                    float4 v3 = __ldg((const float4*)(src + (size_t)s3 * FDIM) + lane);
                    acc.x += (v0.x + v1.x) + (v2.x + v3.x);
                    acc.y += (v0.y + v1.y) + (v2.y + v3.y);
                    acc.z += (v0.z + v1.z) + (v2.z + v3.z);
                    acc.w += (v0.w + v1.w) + (v2.w + v3.w);
                }
                for (; e < end; e++) {
                    int s = __ldg(g_adj + e);
                    float4 v = __ldg((const float4*)(src + (size_t)s * FDIM) + lane);
                    acc.x += v.x; acc.y += v.y; acc.z += v.z; acc.w += v.w;
                }
                float dn = g_dinv[node];
                acc.x = fmaf(acc.x, dn, bv.x);
                acc.y = fmaf(acc.y, dn, bv.y);
                acc.z = fmaf(acc.z, dn, bv.z);
                acc.w = fmaf(acc.w, dn, bv.w);
                if (relu) {
                    acc.x = fmaxf(acc.x, 0.f); acc.y = fmaxf(acc.y, 0.f);
                    acc.z = fmaxf(acc.z, 0.f); acc.w = fmaxf(acc.w, 0.f);
                }
            }
            uint2 hi, lo; split4(acc, hi, lo);
            int off = lr * ROWB + lane * 8;
            *(uint2*)(smem + AHI_OFF + off) = hi;
            *(uint2*)(smem + ALO_OFF + off) = lo;
        }
        __syncthreads();

        // ---- MMA phase ----
        float acc[(NOUT == 128) ? 8 : 3][4];
#pragma unroll
        for (int nt = 0; nt < NT; nt++)
#pragma unroll
            for (int j = 0; j < 4; j++) acc[nt][j] = 0.f;

#pragma unroll
        for (int ks = 0; ks < 8; ks++) {
            const int k0 = ks * 16;
            uint32_t ah[4], al[4];
            uint32_t aoff = (uint32_t)((m0 + a_r) * ROWB + (k0 + a_kh * 8) * 2);
            ldsm_x4(ah[0], ah[1], ah[2], ah[3], sb + AHI_OFF + aoff);
            ldsm_x4(al[0], al[1], al[2], al[3], sb + ALO_OFF + aoff);
#pragma unroll
            for (int nt = 0; nt < NT; nt++) {
                uint32_t boff = (uint32_t)((n0 + nt * 8 + b_r) * ROWB + (k0 + b_kh * 8) * 2);
                uint32_t bh0, bh1, bl0, bl1;
                ldsm_x2(bh0, bh1, sb + BHI_OFF + boff);
                ldsm_x2(bl0, bl1, sb + BLO_OFF + boff);
                mma_bf16(acc[nt][0], acc[nt][1], acc[nt][2], acc[nt][3],
                         ah[0], ah[1], ah[2], ah[3], bh0, bh1);
                mma_bf16(acc[nt][0], acc[nt][1], acc[nt][2], acc[nt][3],
                         ah[0], ah[1], ah[2], ah[3], bl0, bl1);
                mma_bf16(acc[nt][0], acc[nt][1], acc[nt][2], acc[nt][3],
                         al[0], al[1], al[2], al[3], bh0, bh1);
            }
        }
        __syncthreads();

        // ---- epilogue ----
        const int qr = lane >> 2, qc = (lane & 3) * 2;
        int r_a = row0 + m0 + qr, r_b = r_a + 8;
        float dna = (r_a < M) ? g_dinv[r_a] : 0.f;
        float dnb = (r_b < M) ? g_dinv[r_b] : 0.f;
#pragma unroll
        for (int nt = 0; nt < NT; nt++) {
            int col = n0 + nt * 8 + qc;
            if (r_a < M)
                *(float2*)(out + (size_t)r_a * LDOUT + col) =
                    make_float2(acc[nt][0] * dna, acc[nt][1] * dna);
            if (r_b < M)
                *(float2*)(out + (size_t)r_b * LDOUT + col) =
                    make_float2(acc[nt][2] * dnb, acc[nt][3] * dnb);
        }
    }
}

// ---------------- aggregation 40-wide + fused log_softmax ----------------
__global__ void __launch_bounds__(256)
agg40_lsm_kernel(const float* __restrict__ b3, float* __restrict__ out) {
    int node = blockIdx.x * (blockDim.x >> 5) + (threadIdx.x >> 5);
    if (node >= NN) return;
    int lane = threadIdx.x & 31;

    int beg = g_rowptr[node], end = g_rowptr[node + 1];
    float a0 = 0.f, a1 = 0.f;
#pragma unroll 4
    for (int e = beg; e < end; e++) {
        int s = __ldg(g_adj + e);
        const float* r = g_l + (size_t)s * NCLS;
        a0 += __ldg(r + lane);
        if (lane < 8) a1 += __ldg(r + 32 + lane);
    }

    float dn = g_dinv[node];
    float v0 = a0 * dn + __ldg(b3 + lane);
    float v1 = (lane < 8) ? (a1 * dn + __ldg(b3 + 32 + lane)) : -1e30f;

    float m = fmaxf(v0, v1);
#pragma unroll
    for (int off = 16; off; off >>= 1)
        m = fmaxf(m, __shfl_xor_sync(0xffffffffu, m, off));
    float s = __expf(v0 - m) + ((lane < 8) ? __expf(v1 - m) : 0.f);
#pragma unroll
    for (int off = 16; off; off >>= 1)
        s += __shfl_xor_sync(0xffffffffu, s, off);
    float L = __logf(s) + m;

    out[(size_t)node * NCLS + lane] = v0 - L;
    if (lane < 8) out[(size_t)node * NCLS + 32 + lane] = v1 - L;
}

// ---------------- launch ----------------
extern "C" void kernel_launch(void* const* d_in, const int* in_sizes, int n_in,
                              void* d_out, int out_size) {
    const float* x  = (const float*)d_in[0];
    const int*   ei = (const int*)d_in[1];
    const float* W1 = (const float*)d_in[2];
    const float* b1 = (const float*)d_in[3];
    const float* W2 = (const float*)d_in[4];
    const float* b2 = (const float*)d_in[5];
    const float* W3 = (const float*)d_in[6];
    const float* b3 = (const float*)d_in[7];
    float* out = (float*)d_out;

    const int nbScan = (NN + SCAN_BLK - 1) / SCAN_BLK;
    const int gN   = (NN + 255) / 256;
    const int gE   = (NE + 255) / 256;
    const int gET  = (ET + 255) / 256;
    const int gAgg = (NN + 7) / 8;

    const int SMEM128 = BHI_OFF + 2 * 128 * ROWB;  // 139264
    const int SMEM40  = BHI_OFF + 2 * 40 * ROWB;   //  91392
    cudaFuncSetAttribute(gemm1_kernel,
                         cudaFuncAttributeMaxDynamicSharedMemorySize, SMEM128);
    cudaFuncSetAttribute(fused_agg_gemm_kernel<128, 0>,
                         cudaFuncAttributeMaxDynamicSharedMemorySize, SMEM128);
    cudaFuncSetAttribute(fused_agg_gemm_kernel<40, 1>,
                         cudaFuncAttributeMaxDynamicSharedMemorySize, SMEM40);

    // --- graph preprocessing ---
    detect64_kernel<<<1, 256>>>(ei);
    init_deg_kernel<<<gN, 256>>>();
    count_deg_kernel<<<gE, 256>>>(ei);
    calc_dinv_kernel<<<gN, 256>>>();
    scan1_kernel<<<nbScan, SCAN_BLK>>>();
    scan2_kernel<<<1, 256>>>(nbScan);
    scan3_kernel<<<nbScan, SCAN_BLK>>>();
    fill_adj_kernel<<<gET, 256>>>(ei);

    // --- weight pre-pack ---
    pack_w_kernel<<<(128 * 128 + 255) / 256, 256>>>(W1, 128, 0);
    pack_w_kernel<<<(128 * 128 + 255) / 256, 256>>>(W2, 128, 1);
    pack_w_kernel<<<(40 * 128 + 255) / 256, 256>>>(W3, NCLS, 2);

    // --- layer 1: t1 = dinv*(x@W1) ---
    gemm1_kernel<<<148, 512, SMEM128>>>(x, NN);

    // --- layer 2 fused: t2 = dinv*( relu(dinv*agg(t1)+b1) @ W2 ) ---
    fused_agg_gemm_kernel<128, 0><<<148, 512, SMEM128>>>(b1, 1, NN);

    // --- layer 3 fused: l = dinv*( (dinv*agg(t2)+b2) @ W3 ) ---
    fused_agg_gemm_kernel<40, 1><<<148, 512, SMEM40>>>(b2, 0, NN);

    // --- final aggregation + log_softmax ---
    agg40_lsm_kernel<<<gAgg, 256>>>(b3, out);

    (void)in_sizes; (void)n_in; (void)out_size;
}

// round 10
// speedup vs baseline: 1.5828x; 1.0735x over previous
#include <cuda_runtime.h>
#include <cuda_bf16.h>
#include <math.h>
#include <stdint.h>

// Problem constants (fixed by the dataset)
#define NN 169343            // nodes
#define NE 1166243           // edges
#define ET (NE + NN)         // edges + self loops = 1335586
#define FDIM 128
#define NCLS 40
#define NTILES ((NN + 127) / 128)   // 1324

#define ROWS_PAD 136         // bf16 elements per padded row
#define ROWB 272             // bytes per padded row

// ---------------- device scratch (no cudaMalloc allowed) ----------------
__device__ int   g_is64;
__device__ int   g_deg[NN];
__device__ int   g_fill[NN];
__device__ int   g_rowptr[NN + 1];
__device__ int   g_bsum[256];
__device__ int   g_adj[ET];
__device__ float g_dinv[NN];
__device__ float g_ta[(size_t)NN * FDIM]; // layer-1 GEMM output t1
__device__ float g_tb[(size_t)NN * FDIM]; // layer-2 GEMM output t2
__device__ float g_l[(size_t)NN * NCLS];  // layer-3 GEMM output

// Pre-packed bf16 weight images ([n][k], padded rows, hi/lo split)
__device__ unsigned short g_Bh1[128 * ROWS_PAD], g_Bl1[128 * ROWS_PAD];
__device__ unsigned short g_Bh2[128 * ROWS_PAD], g_Bl2[128 * ROWS_PAD];
__device__ unsigned short g_Bh3[40 * ROWS_PAD],  g_Bl3[40 * ROWS_PAD];

// ---------------- PTX helpers (portable sm_80+ class only) ----------------
__device__ __forceinline__ uint32_t smem_u32(const void* p) {
    uint32_t a;
    asm("{ .reg .u64 t; cvta.to.shared.u64 t, %1; cvt.u32.u64 %0, t; }"
        : "=r"(a) : "l"(p));
    return a;
}

__device__ __forceinline__ void ldsm_x4(uint32_t& r0, uint32_t& r1,
                                        uint32_t& r2, uint32_t& r3, uint32_t addr) {
    asm volatile("ldmatrix.sync.aligned.m8n8.x4.shared.b16 {%0,%1,%2,%3}, [%4];"
                 : "=r"(r0), "=r"(r1), "=r"(r2), "=r"(r3) : "r"(addr));
}

__device__ __forceinline__ void ldsm_x2(uint32_t& r0, uint32_t& r1, uint32_t addr) {
    asm volatile("ldmatrix.sync.aligned.m8n8.x2.shared.b16 {%0,%1}, [%2];"
                 : "=r"(r0), "=r"(r1) : "r"(addr));
}

__device__ __forceinline__ void mma_bf16(float& d0, float& d1, float& d2, float& d3,
                                         uint32_t a0, uint32_t a1, uint32_t a2, uint32_t a3,
                                         uint32_t b0, uint32_t b1) {
    asm volatile(
        "mma.sync.aligned.m16n8k16.row.col.f32.bf16.bf16.f32 "
        "{%0,%1,%2,%3}, {%4,%5,%6,%7}, {%8,%9}, {%0,%1,%2,%3};"
        : "+f"(d0), "+f"(d1), "+f"(d2), "+f"(d3)
        : "r"(a0), "r"(a1), "r"(a2), "r"(a3), "r"(b0), "r"(b1));
}

// split fp32 float4 -> bf16 hi/lo packed uint2 pair
__device__ __forceinline__ void split4(const float4& v, uint2& hi, uint2& lo) {
    unsigned short h0, h1, h2, h3;
    asm("cvt.rn.bf16.f32 %0, %1;" : "=h"(h0) : "f"(v.x));
    asm("cvt.rn.bf16.f32 %0, %1;" : "=h"(h1) : "f"(v.y));
    asm("cvt.rn.bf16.f32 %0, %1;" : "=h"(h2) : "f"(v.z));
    asm("cvt.rn.bf16.f32 %0, %1;" : "=h"(h3) : "f"(v.w));
    float r0 = v.x - __uint_as_float((unsigned)h0 << 16);
    float r1 = v.y - __uint_as_float((unsigned)h1 << 16);
    float r2 = v.z - __uint_as_float((unsigned)h2 << 16);
    float r3 = v.w - __uint_as_float((unsigned)h3 << 16);
    hi.x = (uint32_t)h0 | ((uint32_t)h1 << 16);
    hi.y = (uint32_t)h2 | ((uint32_t)h3 << 16);
    asm("cvt.rn.bf16x2.f32 %0, %1, %2;" : "=r"(lo.x) : "f"(r1), "f"(r0));
    asm("cvt.rn.bf16x2.f32 %0, %1, %2;" : "=r"(lo.y) : "f"(r3), "f"(r2));
}

__device__ __forceinline__ int edge_src(const int* w, int e) {
    return g_is64 ? w[2 * e] : w[e];
}
__device__ __forceinline__ int edge_dst(const int* w, int e) {
    return g_is64 ? w[2 * (NE + e)] : w[NE + e];
}

// ---------------- preprocessing ----------------
// init degrees/fill; block 0 also detects edge_index dtype
__global__ void init_deg_kernel(const int* __restrict__ w) {
    int i = blockIdx.x * blockDim.x + threadIdx.x;
    if (i < NN) { g_deg[i] = 1; g_fill[i] = 0; }
    if (blockIdx.x == 0) {
        __shared__ int bad;
        if (threadIdx.x == 0) bad = 0;
        __syncthreads();
        for (int j = threadIdx.x; j < 1024; j += blockDim.x)
            if (w[2 * j + 1] != 0) atomicAdd(&bad, 1);
        __syncthreads();
        if (threadIdx.x == 0) g_is64 = (bad == 0) ? 1 : 0;
    }
}

__global__ void count_deg_kernel(const int* __restrict__ w) {
    int e = blockIdx.x * blockDim.x + threadIdx.x;
    if (e >= NE) return;
    atomicAdd(&g_deg[edge_dst(w, e)], 1);
}

#define SCAN_BLK 1024
__global__ void scan1_kernel() {   // also computes dinv
    __shared__ int sh[SCAN_BLK];
    int i = blockIdx.x * SCAN_BLK + threadIdx.x;
    int v = (i < NN) ? g_deg[i] : 0;
    if (i < NN) g_dinv[i] = rsqrtf((float)v);
    sh[threadIdx.x] = v;
    __syncthreads();
    for (int off = 1; off < SCAN_BLK; off <<= 1) {
        int add = (threadIdx.x >= off) ? sh[threadIdx.x - off] : 0;
        __syncthreads();
        sh[threadIdx.x] += add;
        __syncthreads();
    }
    if (i < NN) g_rowptr[i + 1] = sh[threadIdx.x];
    if (threadIdx.x == SCAN_BLK - 1) g_bsum[blockIdx.x] = sh[threadIdx.x];
}

__global__ void scan2_kernel(int nb) {
    __shared__ int sh[256];
    int t = threadIdx.x;
    sh[t] = (t < nb) ? g_bsum[t] : 0;
    __syncthreads();
    if (t == 0) {
        int run = 0;
        for (int i = 0; i < nb; i++) { int v = sh[i]; sh[i] = run; run += v; }
    }
    __syncthreads();
    if (t < nb) g_bsum[t] = sh[t];
}

__global__ void scan3_kernel() {
    int i = blockIdx.x * blockDim.x + threadIdx.x;
    if (i == 0) g_rowptr[0] = 0;
    if (i < NN) g_rowptr[i + 1] += g_bsum[i >> 10];
}

__global__ void fill_adj_kernel(const int* __restrict__ w) {
    int e = blockIdx.x * blockDim.x + threadIdx.x;
    if (e >= ET) return;
    int s, d;
    if (e < NE) { s = edge_src(w, e); d = edge_dst(w, e); }
    else        { s = d = e - NE; }
    int pos = g_rowptr[d] + atomicAdd(&g_fill[d], 1);
    g_adj[pos] = s;
}

// ---------------- weight pre-pack (all three in one launch) ----------------
__global__ void pack_all_kernel(const float* __restrict__ W1,
                                const float* __restrict__ W2,
                                const float* __restrict__ W3) {
    int idx = blockIdx.x * blockDim.x + threadIdx.x;
    const float* W;
    unsigned short *bh, *bl;
    int Nout;
    if (idx < 16384)        { W = W1; bh = g_Bh1; bl = g_Bl1; Nout = 128; }
    else if (idx < 32768)   { idx -= 16384; W = W2; bh = g_Bh2; bl = g_Bl2; Nout = 128; }
    else if (idx < 37888)   { idx -= 32768; W = W3; bh = g_Bh3; bl = g_Bl3; Nout = 40; }
    else return;
    int n = idx >> 7, k = idx & 127;
    float v = W[k * Nout + n];
    unsigned short h; asm("cvt.rn.bf16.f32 %0, %1;" : "=h"(h) : "f"(v));
    float hf = __uint_as_float(((unsigned)h) << 16);
    float rres = v - hf;
    unsigned short l; asm("cvt.rn.bf16.f32 %0, %1;" : "=h"(l) : "f"(rres));
    bh[n * ROWS_PAD + k] = h;
    bl[n * ROWS_PAD + k] = l;
}

// smem layout: AHI @0 (34816), ALO @34816, BHI @69632, BLO @69632+BBYTES
#define AHI_OFF 0
#define ALO_OFF 34816
#define BHI_OFF 69632

// ---------------- GEMM1: g_ta = dinv[row] * (x @ W1) ----------------
__global__ void __launch_bounds__(512, 1)
gemm1_kernel(const float* __restrict__ A, int M) {
    extern __shared__ __align__(16) char smem[];
    const int BLO_OFF = BHI_OFF + 128 * ROWB;
    const uint32_t sb = smem_u32(smem);
    const int tid = threadIdx.x, wid = tid >> 5, lane = tid & 31;

    for (int i = tid; i < (128 * ROWB) / 16; i += 512) {
        ((float4*)(smem + BHI_OFF))[i] = ((const float4*)g_Bh1)[i];
        ((float4*)(smem + BLO_OFF))[i] = ((const float4*)g_Bl1)[i];
    }

    const int m0 = (wid & 7) * 16;
    const int n0 = (wid >> 3) * 64;
    const int a_r = lane & 15, a_kh = lane >> 4;
    const int b_r = lane & 7,  b_kh = (lane >> 3) & 1;

    for (int tile = blockIdx.x; tile < NTILES; tile += gridDim.x) {
        const int row0 = tile * 128;

#pragma unroll
        for (int i = 0; i < 8; i++) {
            int idx = tid + i * 512;
            int r = idx >> 5, c4 = (idx & 31) << 2;
            int grow = row0 + r;
            float4 v = make_float4(0.f, 0.f, 0.f, 0.f);
            if (grow < M) v = *(const float4*)(A + (size_t)grow * FDIM + c4);
            uint2 hi, lo; split4(v, hi, lo);
            int off = r * ROWB + c4 * 2;
            *(uint2*)(smem + AHI_OFF + off) = hi;
            *(uint2*)(smem + ALO_OFF + off) = lo;
        }
        __syncthreads();

        float acc[8][4];
#pragma unroll
        for (int nt = 0; nt < 8; nt++)
#pragma unroll
            for (int j = 0; j < 4; j++) acc[nt][j] = 0.f;

#pragma unroll
        for (int ks = 0; ks < 8; ks++) {
            const int k0 = ks * 16;
            uint32_t ah[4], al[4];
            uint32_t aoff = (uint32_t)((m0 + a_r) * ROWB + (k0 + a_kh * 8) * 2);
            ldsm_x4(ah[0], ah[1], ah[2], ah[3], sb + AHI_OFF + aoff);
            ldsm_x4(al[0], al[1], al[2], al[3], sb + ALO_OFF + aoff);
#pragma unroll
            for (int nt = 0; nt < 8; nt++) {
                uint32_t boff = (uint32_t)((n0 + nt * 8 + b_r) * ROWB + (k0 + b_kh * 8) * 2);
                uint32_t bh0, bh1, bl0, bl1;
                ldsm_x2(bh0, bh1, sb + BHI_OFF + boff);
                ldsm_x2(bl0, bl1, sb + BLO_OFF + boff);
                mma_bf16(acc[nt][0], acc[nt][1], acc[nt][2], acc[nt][3],
                         ah[0], ah[1], ah[2], ah[3], bh0, bh1);
                mma_bf16(acc[nt][0], acc[nt][1], acc[nt][2], acc[nt][3],
                         ah[0], ah[1], ah[2], ah[3], bl0, bl1);
                mma_bf16(acc[nt][0], acc[nt][1], acc[nt][2], acc[nt][3],
                         al[0], al[1], al[2], al[3], bh0, bh1);
            }
        }
        __syncthreads();

        const int qr = lane >> 2, qc = (lane & 3) * 2;
        int r_a = row0 + m0 + qr, r_b = r_a + 8;
        float dna = (r_a < M) ? g_dinv[r_a] : 0.f;
        float dnb = (r_b < M) ? g_dinv[r_b] : 0.f;
#pragma unroll
        for (int nt = 0; nt < 8; nt++) {
            int col = n0 + nt * 8 + qc;
            if (r_a < M)
                *(float2*)(g_ta + (size_t)r_a * FDIM + col) =
                    make_float2(acc[nt][0] * dna, acc[nt][1] * dna);
            if (r_b < M)
                *(float2*)(g_ta + (size_t)r_b * FDIM + col) =
                    make_float2(acc[nt][2] * dnb, acc[nt][3] * dnb);
        }
    }
}

// ---------------- fused: agg(src) -> bias/relu -> @W -> dinv -> dst ----------------
template<int NOUT, int SRCSEL>
__global__ void __launch_bounds__(512, 1)
fused_agg_gemm_kernel(const float* __restrict__ bias, int relu, int M) {
    extern __shared__ __align__(16) char smem[];
    const int BBYTES = NOUT * ROWB;
    const int BLO_OFF = BHI_OFF + BBYTES;
    const uint32_t sb = smem_u32(smem);
    const int tid = threadIdx.x, wid = tid >> 5, lane = tid & 31;

    const float* __restrict__ src = SRCSEL ? g_tb : g_ta;
    float* __restrict__ out = (NOUT == 128) ? g_tb : g_l;
    const int LDOUT = (NOUT == 128) ? FDIM : NCLS;
    const unsigned short* bh = SRCSEL ? g_Bh3 : g_Bh2;
    const unsigned short* bl = SRCSEL ? g_Bl3 : g_Bl2;

    for (int i = tid; i < BBYTES / 16; i += 512) {
        ((float4*)(smem + BHI_OFF))[i] = ((const float4*)bh)[i];
        ((float4*)(smem + BLO_OFF))[i] = ((const float4*)bl)[i];
    }

    const int m0 = (wid & 7) * 16;
    const int nhalf = wid >> 3;
    const int n0 = (NOUT == 128) ? nhalf * 64 : nhalf * 24;
    const int NT = (NOUT == 128) ? 8 : (nhalf ? 2 : 3);
    const int a_r = lane & 15, a_kh = lane >> 4;
    const int b_r = lane & 7,  b_kh = (lane >> 3) & 1;

    const float4 bv = __ldg((const float4*)bias + lane);

    for (int tile = blockIdx.x; tile < NTILES; tile += gridDim.x) {
        const int row0 = tile * 128;

        // ---- gather phase: warp w -> rows w*8 .. w*8+7 (8-edge unrolled) ----
#pragma unroll
        for (int r8 = 0; r8 < 8; r8++) {
            int lr = wid * 8 + r8;
            int node = row0 + lr;
            float4 acc = make_float4(0.f, 0.f, 0.f, 0.f);
            if (node < M) {
                int beg = g_rowptr[node], end = g_rowptr[node + 1];
                int e = beg;
                for (; e + 8 <= end; e += 8) {
                    int s[8];
#pragma unroll
                    for (int j = 0; j < 8; j++) s[j] = __ldg(g_adj + e + j);
                    float4 v[8];
#pragma unroll
                    for (int j = 0; j < 8; j++)
                        v[j] = __ldg((const float4*)(src + (size_t)s[j] * FDIM) + lane);
#pragma unroll
                    for (int j = 0; j < 8; j++) {
                        acc.x += v[j].x; acc.y += v[j].y;
                        acc.z += v[j].z; acc.w += v[j].w;
                    }
                }
                for (; e + 2 <= end; e += 2) {
                    int s0 = __ldg(g_adj + e), s1 = __ldg(g_adj + e + 1);
                    float4 v0 = __ldg((const float4*)(src + (size_t)s0 * FDIM) + lane);
                    float4 v1 = __ldg((const float4*)(src + (size_t)s1 * FDIM) + lane);
                    acc.x += v0.x + v1.x; acc.y += v0.y + v1.y;
                    acc.z += v0.z + v1.z; acc.w += v0.w + v1.w;
                }
                if (e < end) {
                    int s0 = __ldg(g_adj + e);
                    float4 v0 = __ldg((const float4*)(src + (size_t)s0 * FDIM) + lane);
                    acc.x += v0.x; acc.y += v0.y; acc.z += v0.z; acc.w += v0.w;
                }
                float dn = g_dinv[node];
                acc.x = fmaf(acc.x, dn, bv.x);
                acc.y = fmaf(acc.y, dn, bv.y);
                acc.z = fmaf(acc.z, dn, bv.z);
                acc.w = fmaf(acc.w, dn, bv.w);
                if (relu) {
                    acc.x = fmaxf(acc.x, 0.f); acc.y = fmaxf(acc.y, 0.f);
                    acc.z = fmaxf(acc.z, 0.f); acc.w = fmaxf(acc.w, 0.f);
                }
            }
            uint2 hi, lo; split4(acc, hi, lo);
            int off = lr * ROWB + lane * 8;
            *(uint2*)(smem + AHI_OFF + off) = hi;
            *(uint2*)(smem + ALO_OFF + off) = lo;
        }
        __syncthreads();

        // ---- MMA phase ----
        float acc[(NOUT == 128) ? 8 : 3][4];
#pragma unroll
        for (int nt = 0; nt < NT; nt++)
#pragma unroll
            for (int j = 0; j < 4; j++) acc[nt][j] = 0.f;

#pragma unroll
        for (int ks = 0; ks < 8; ks++) {
            const int k0 = ks * 16;
            uint32_t ah[4], al[4];
            uint32_t aoff = (uint32_t)((m0 + a_r) * ROWB + (k0 + a_kh * 8) * 2);
            ldsm_x4(ah[0], ah[1], ah[2], ah[3], sb + AHI_OFF + aoff);
            ldsm_x4(al[0], al[1], al[2], al[3], sb + ALO_OFF + aoff);
#pragma unroll
            for (int nt = 0; nt < NT; nt++) {
                uint32_t boff = (uint32_t)((n0 + nt * 8 + b_r) * ROWB + (k0 + b_kh * 8) * 2);
                uint32_t bh0, bh1, bl0, bl1;
                ldsm_x2(bh0, bh1, sb + BHI_OFF + boff);
                ldsm_x2(bl0, bl1, sb + BLO_OFF + boff);
                mma_bf16(acc[nt][0], acc[nt][1], acc[nt][2], acc[nt][3],
                         ah[0], ah[1], ah[2], ah[3], bh0, bh1);
                mma_bf16(acc[nt][0], acc[nt][1], acc[nt][2], acc[nt][3],
                         ah[0], ah[1], ah[2], ah[3], bl0, bl1);
                mma_bf16(acc[nt][0], acc[nt][1], acc[nt][2], acc[nt][3],
                         al[0], al[1], al[2], al[3], bh0, bh1);
            }
        }
        __syncthreads();

        // ---- epilogue ----
        const int qr = lane >> 2, qc = (lane & 3) * 2;
        int r_a = row0 + m0 + qr, r_b = r_a + 8;
        float dna = (r_a < M) ? g_dinv[r_a] : 0.f;
        float dnb = (r_b < M) ? g_dinv[r_b] : 0.f;
#pragma unroll
        for (int nt = 0; nt < NT; nt++) {
            int col = n0 + nt * 8 + qc;
            if (r_a < M)
                *(float2*)(out + (size_t)r_a * LDOUT + col) =
                    make_float2(acc[nt][0] * dna, acc[nt][1] * dna);
            if (r_b < M)
                *(float2*)(out + (size_t)r_b * LDOUT + col) =
                    make_float2(acc[nt][2] * dnb, acc[nt][3] * dnb);
        }
    }
}

// ---------------- aggregation 40-wide + fused log_softmax ----------------
__global__ void __launch_bounds__(256)
agg40_lsm_kernel(const float* __restrict__ b3, float* __restrict__ out) {
    int node = blockIdx.x * (blockDim.x >> 5) + (threadIdx.x >> 5);
    if (node >= NN) return;
    int lane = threadIdx.x & 31;

    int beg = g_rowptr[node], end = g_rowptr[node + 1];
    float a0 = 0.f, a1 = 0.f;
    int e = beg;
    for (; e + 8 <= end; e += 8) {
        int s[8];
#pragma unroll
        for (int j = 0; j < 8; j++) s[j] = __ldg(g_adj + e + j);
        float v0[8], v1[8];
#pragma unroll
        for (int j = 0; j < 8; j++) {
            const float* r = g_l + (size_t)s[j] * NCLS;
            v0[j] = __ldg(r + lane);
            v1[j] = (lane < 8) ? __ldg(r + 32 + lane) : 0.f;
        }
#pragma unroll
        for (int j = 0; j < 8; j++) { a0 += v0[j]; a1 += v1[j]; }
    }
    for (; e < end; e++) {
        int s = __ldg(g_adj + e);
        const float* r = g_l + (size_t)s * NCLS;
        a0 += __ldg(r + lane);
        if (lane < 8) a1 += __ldg(r + 32 + lane);
    }

    float dn = g_dinv[node];
    float v0 = a0 * dn + __ldg(b3 + lane);
    float v1 = (lane < 8) ? (a1 * dn + __ldg(b3 + 32 + lane)) : -1e30f;

    float m = fmaxf(v0, v1);
#pragma unroll
    for (int off = 16; off; off >>= 1)
        m = fmaxf(m, __shfl_xor_sync(0xffffffffu, m, off));
    float s = __expf(v0 - m) + ((lane < 8) ? __expf(v1 - m) : 0.f);
#pragma unroll
    for (int off = 16; off; off >>= 1)
        s += __shfl_xor_sync(0xffffffffu, s, off);
    float L = __logf(s) + m;

    out[(size_t)node * NCLS + lane] = v0 - L;
    if (lane < 8) out[(size_t)node * NCLS + 32 + lane] = v1 - L;
}

// ---------------- launch ----------------
extern "C" void kernel_launch(void* const* d_in, const int* in_sizes, int n_in,
                              void* d_out, int out_size) {
    const float* x  = (const float*)d_in[0];
    const int*   ei = (const int*)d_in[1];
    const float* W1 = (const float*)d_in[2];
    const float* b1 = (const float*)d_in[3];
    const float* W2 = (const float*)d_in[4];
    const float* b2 = (const float*)d_in[5];
    const float* W3 = (const float*)d_in[6];
    const float* b3 = (const float*)d_in[7];
    float* out = (float*)d_out;

    const int nbScan = (NN + SCAN_BLK - 1) / SCAN_BLK;
    const int gN   = (NN + 255) / 256;
    const int gE   = (NE + 255) / 256;
    const int gET  = (ET + 255) / 256;
    const int gAgg = (NN + 7) / 8;

    const int SMEM128 = BHI_OFF + 2 * 128 * ROWB;  // 139264
    const int SMEM40  = BHI_OFF + 2 * 40 * ROWB;   //  91392
    cudaFuncSetAttribute(gemm1_kernel,
                         cudaFuncAttributeMaxDynamicSharedMemorySize, SMEM128);
    cudaFuncSetAttribute(fused_agg_gemm_kernel<128, 0>,
                         cudaFuncAttributeMaxDynamicSharedMemorySize, SMEM128);
    cudaFuncSetAttribute(fused_agg_gemm_kernel<40, 1>,
                         cudaFuncAttributeMaxDynamicSharedMemorySize, SMEM40);

    // --- graph preprocessing (dtype detect fused into init; dinv into scan1) ---
    init_deg_kernel<<<gN, 256>>>(ei);
    count_deg_kernel<<<gE, 256>>>(ei);
    scan1_kernel<<<nbScan, SCAN_BLK>>>();
    scan2_kernel<<<1, 256>>>(nbScan);
    scan3_kernel<<<nbScan, SCAN_BLK>>>();
    fill_adj_kernel<<<gET, 256>>>(ei);

    // --- weight pre-pack (single launch) ---
    pack_all_kernel<<<148, 256>>>(W1, W2, W3);

    // --- layer 1: t1 = dinv*(x@W1) ---
    gemm1_kernel<<<148, 512, SMEM128>>>(x, NN);

    // --- layer 2 fused: t2 = dinv*( relu(dinv*agg(t1)+b1) @ W2 ) ---
    fused_agg_gemm_kernel<128, 0><<<148, 512, SMEM128>>>(b1, 1, NN);

    // --- layer 3 fused: l = dinv*( (dinv*agg(t2)+b2) @ W3 ) ---
    fused_agg_gemm_kernel<40, 1><<<148, 512, SMEM40>>>(b2, 0, NN);

    // --- final aggregation + log_softmax ---
    agg40_lsm_kernel<<<gAgg, 256>>>(b3, out);

    (void)in_sizes; (void)n_in; (void)out_size;
}